// round 1
// baseline (speedup 1.0000x reference)
#include <cuda_runtime.h>
#include <cstdint>

#define NVOX   200000
#define NP     100000
#define KK     27
#define CCH    64          // channels (in == out == 64)
#define TP     64          // pairs per block tile
#define XSTRIDE 68         // padded row stride (floats) for gathered X tile

// ---------------------------------------------------------------------------
// Global scratch for BN statistics (no allocations allowed): sum[64], sumsq[64]
// ---------------------------------------------------------------------------
__device__ float g_stats[2 * CCH];

__global__ void zero_stats_kernel() {
    int t = threadIdx.x;
    if (t < 2 * CCH) g_stats[t] = 0.0f;
}

// ---------------------------------------------------------------------------
// red.global.add.v4.f32 helper (sm_90+ vector reduction, no return value)
// ---------------------------------------------------------------------------
__device__ __forceinline__ void red_add_v4(float* ptr, float a, float b, float c, float d) {
    asm volatile("red.global.add.v4.f32 [%0], {%1, %2, %3, %4};"
                 :: "l"(__cvta_generic_to_global(ptr)),
                    "f"(a), "f"(b), "f"(c), "f"(d)
                 : "memory");
}

// ---------------------------------------------------------------------------
// Conv kernel: one block = one (k, 64-pair tile). Gather X rows into smem,
// register-blocked FFMA GEMM against W[k] in smem, atomic scatter-add.
//   warp w handles pairs [w*8, w*8+8); thread (pr = lane>>3, cg = lane&7)
//   owns pairs {w*8+pr, w*8+pr+4} x output cols [cg*8, cg*8+8).
// ---------------------------------------------------------------------------
__global__ __launch_bounds__(256) void conv_kernel(
    const float* __restrict__ x,      // [NVOX, 64]
    const float* __restrict__ w,      // [K, 64, 64]
    const int*   __restrict__ kin,    // [K, NP]
    const int*   __restrict__ kout,   // [K, NP]
    float*       __restrict__ out)    // [NVOX, 64] accumulator (pre-zeroed)
{
    __shared__ float Wsh[CCH * CCH];          // 16 KB, W[i][c] row-major
    __shared__ float Xsh[TP * XSTRIDE];       // 17 KB, gathered rows (padded)
    __shared__ int   sIn[TP];
    __shared__ int   sOut[TP];

    const int k     = blockIdx.y;
    const int pbase = blockIdx.x * TP;
    const int tid   = threadIdx.x;

    // ---- load weight slice W[k] (coalesced float4) ----
    {
        const float4* wk  = (const float4*)(w + (size_t)k * CCH * CCH);
        float4*       Ws4 = (float4*)Wsh;
        #pragma unroll
        for (int i = tid; i < CCH * CCH / 4; i += 256) Ws4[i] = wk[i];
    }

    // ---- load pair indices ----
    if (tid < TP) {
        int p = pbase + tid;
        bool valid = (p < NP);
        sIn[tid]  = valid ? kin[(size_t)k * NP + p] : -1;
        sOut[tid] = valid ? kout[(size_t)k * NP + p] : 0;
    }
    __syncthreads();

    // ---- gather X rows: thread handles pair p = tid/4, cols [q*16, q*16+16) ----
    {
        int p = tid >> 2;
        int q = tid & 3;
        int in = sIn[p];
        float4* dst = (float4*)(Xsh + p * XSTRIDE + q * 16);
        if (in >= 0) {
            const float4* src = (const float4*)(x + (size_t)in * CCH + q * 16);
            float4 v0 = src[0], v1 = src[1], v2 = src[2], v3 = src[3];
            dst[0] = v0; dst[1] = v1; dst[2] = v2; dst[3] = v3;
        } else {
            float4 z = make_float4(0.f, 0.f, 0.f, 0.f);
            dst[0] = z; dst[1] = z; dst[2] = z; dst[3] = z;
        }
    }
    __syncthreads();

    // ---- register-blocked GEMM ----
    const int warp = tid >> 5;
    const int lane = tid & 31;
    const int pr   = lane >> 3;      // 0..3
    const int cg   = lane & 7;       // 0..7
    const int p0   = warp * 8 + pr;
    const int p1   = p0 + 4;
    const int cw   = cg * 2;         // float4 column index into W row

    float acc0[8] = {0.f,0.f,0.f,0.f,0.f,0.f,0.f,0.f};
    float acc1[8] = {0.f,0.f,0.f,0.f,0.f,0.f,0.f,0.f};

    const float4* X0 = (const float4*)(Xsh + p0 * XSTRIDE);
    const float4* X1 = (const float4*)(Xsh + p1 * XSTRIDE);
    const float4* W4 = (const float4*)Wsh;   // row i at W4[i*16 + cw]

    #define INNER_STEP(XA, XB, I)                                   \
        {                                                           \
            float4 wA = W4[(I) * 16 + cw];                          \
            float4 wB = W4[(I) * 16 + cw + 1];                      \
            acc0[0] += (XA) * wA.x;  acc0[1] += (XA) * wA.y;        \
            acc0[2] += (XA) * wA.z;  acc0[3] += (XA) * wA.w;        \
            acc0[4] += (XA) * wB.x;  acc0[5] += (XA) * wB.y;        \
            acc0[6] += (XA) * wB.z;  acc0[7] += (XA) * wB.w;        \
            acc1[0] += (XB) * wA.x;  acc1[1] += (XB) * wA.y;        \
            acc1[2] += (XB) * wA.z;  acc1[3] += (XB) * wA.w;        \
            acc1[4] += (XB) * wB.x;  acc1[5] += (XB) * wB.y;        \
            acc1[6] += (XB) * wB.z;  acc1[7] += (XB) * wB.w;        \
        }

    #pragma unroll 4
    for (int i4 = 0; i4 < 16; ++i4) {
        float4 xa = X0[i4];
        float4 xb = X1[i4];
        int ib = i4 * 4;
        INNER_STEP(xa.x, xb.x, ib + 0);
        INNER_STEP(xa.y, xb.y, ib + 1);
        INNER_STEP(xa.z, xb.z, ib + 2);
        INNER_STEP(xa.w, xb.w, ib + 3);
    }
    #undef INNER_STEP

    // ---- atomic scatter-add (invalid pairs add 0.0 to row 0: harmless) ----
    {
        int o0 = sOut[p0];
        int o1 = sOut[p1];
        float* d0 = out + (size_t)o0 * CCH + cg * 8;
        float* d1 = out + (size_t)o1 * CCH + cg * 8;
        red_add_v4(d0,     acc0[0], acc0[1], acc0[2], acc0[3]);
        red_add_v4(d0 + 4, acc0[4], acc0[5], acc0[6], acc0[7]);
        red_add_v4(d1,     acc1[0], acc1[1], acc1[2], acc1[3]);
        red_add_v4(d1 + 4, acc1[4], acc1[5], acc1[6], acc1[7]);
    }
}

// ---------------------------------------------------------------------------
// BN stats: per-column sum and sum-of-squares over NVOX rows.
// Thread (cg = tid&15, r0 = tid>>4) reads float4 at column group cg.
// ---------------------------------------------------------------------------
__global__ __launch_bounds__(256) void stats_kernel(const float* __restrict__ y) {
    __shared__ float4 shs[256];
    __shared__ float4 shq[256];
    const int tid = threadIdx.x;
    const int cg  = tid & 15;
    const int r0  = tid >> 4;

    float4 s = make_float4(0.f, 0.f, 0.f, 0.f);
    float4 q = make_float4(0.f, 0.f, 0.f, 0.f);
    const float4* y4 = (const float4*)y;

    for (int row = blockIdx.x * 16 + r0; row < NVOX; row += gridDim.x * 16) {
        float4 v = y4[row * 16 + cg];
        s.x += v.x; s.y += v.y; s.z += v.z; s.w += v.w;
        q.x += v.x * v.x; q.y += v.y * v.y; q.z += v.z * v.z; q.w += v.w * v.w;
    }
    shs[tid] = s; shq[tid] = q;
    __syncthreads();

    #pragma unroll
    for (int off = 128; off >= 16; off >>= 1) {
        if (tid < off) {
            float4 a = shs[tid], b = shs[tid + off];
            a.x += b.x; a.y += b.y; a.z += b.z; a.w += b.w;
            shs[tid] = a;
            float4 c = shq[tid], d = shq[tid + off];
            c.x += d.x; c.y += d.y; c.z += d.z; c.w += d.w;
            shq[tid] = c;
        }
        __syncthreads();
    }

    if (tid < 16) {
        float4 a = shs[tid], c = shq[tid];
        int col = tid * 4;
        atomicAdd(&g_stats[col + 0], a.x);
        atomicAdd(&g_stats[col + 1], a.y);
        atomicAdd(&g_stats[col + 2], a.z);
        atomicAdd(&g_stats[col + 3], a.w);
        atomicAdd(&g_stats[CCH + col + 0], c.x);
        atomicAdd(&g_stats[CCH + col + 1], c.y);
        atomicAdd(&g_stats[CCH + col + 2], c.z);
        atomicAdd(&g_stats[CCH + col + 3], c.w);
    }
}

// ---------------------------------------------------------------------------
// Fused BN (train-mode batch stats, biased var) + ReLU, in place on d_out.
// ---------------------------------------------------------------------------
__global__ __launch_bounds__(256) void norm_kernel(
    float* __restrict__ y,
    const float* __restrict__ gamma,
    const float* __restrict__ beta)
{
    __shared__ float sc[CCH];
    __shared__ float bi[CCH];
    const int tid = threadIdx.x;
    if (tid < CCH) {
        const float invN = 1.0f / (float)NVOX;
        float mean = g_stats[tid] * invN;
        float var  = g_stats[CCH + tid] * invN - mean * mean;
        float s = rsqrtf(var + 1e-5f) * gamma[tid];
        sc[tid] = s;
        bi[tid] = beta[tid] - mean * s;
    }
    __syncthreads();

    const int total4 = NVOX * 16;   // float4 elements
    float4* y4 = (float4*)y;
    for (int idx = blockIdx.x * 256 + tid; idx < total4; idx += gridDim.x * 256) {
        int c = (idx & 15) * 4;
        float4 v = y4[idx];
        v.x = fmaxf(fmaf(v.x, sc[c + 0], bi[c + 0]), 0.f);
        v.y = fmaxf(fmaf(v.y, sc[c + 1], bi[c + 1]), 0.f);
        v.z = fmaxf(fmaf(v.z, sc[c + 2], bi[c + 2]), 0.f);
        v.w = fmaxf(fmaf(v.w, sc[c + 3], bi[c + 3]), 0.f);
        y4[idx] = v;
    }
}

// ---------------------------------------------------------------------------
// Launch: memset out -> conv (gather/GEMM/scatter) -> zero stats -> stats ->
//         fused BN+ReLU (in place). All on the default stream (capturable).
// ---------------------------------------------------------------------------
extern "C" void kernel_launch(void* const* d_in, const int* in_sizes, int n_in,
                              void* d_out, int out_size) {
    const float* x     = (const float*)d_in[0];
    const float* w     = (const float*)d_in[1];
    const float* gamma = (const float*)d_in[2];
    const float* beta  = (const float*)d_in[3];
    const int*   kin   = (const int*)d_in[4];
    const int*   kout  = (const int*)d_in[5];
    float*       out   = (float*)d_out;

    cudaMemsetAsync(out, 0, (size_t)NVOX * CCH * sizeof(float), 0);

    dim3 cgrid((NP + TP - 1) / TP, KK);
    conv_kernel<<<cgrid, 256>>>(x, w, kin, kout, out);

    zero_stats_kernel<<<1, 128>>>();
    stats_kernel<<<512, 256>>>(out);
    norm_kernel<<<2048, 256>>>(out, gamma, beta);
}

// round 3
// speedup vs baseline: 2.8779x; 2.8779x over previous
#include <cuda_runtime.h>
#include <cstdint>

#define NVOX   200000
#define NP     100000
#define KK     27
#define CCH    64
#define TP     128                        // pairs per block (GEMM M)
#define NBLK   ((NP + TP - 1) / TP)       // 782
#define XPAD   68                         // padded row stride (floats)

// smem layout (bytes, dynamic):
//   [0,512)        sIn[128]
//   [512,1024)     sOut[128]
//   [1024, +34816) Xsh  [128][68] f32 (tf32 bits)
//   [35840,+17408) Wt   [64][68]  f32 (tf32 bits), row = out-channel n, col = in-channel
#define SM_SIN  0
#define SM_SOUT 512
#define SM_X    1024
#define SM_W    35840
#define SMEM_TOTAL 53248

__device__ float g_stats[2 * CCH];       // BN sum / sumsq
__device__ float g_wt[KK * CCH * CCH];   // W transposed [k][outc][inc], tf32-rounded

__device__ __forceinline__ uint32_t f2tf32(float f) {
    uint32_t r;
    asm("cvt.rna.tf32.f32 %0, %1;" : "=r"(r) : "f"(f));
    return r;
}
__device__ __forceinline__ void red_add_v4(float* ptr, float a, float b, float c, float d) {
    asm volatile("red.global.add.v4.f32 [%0], {%1, %2, %3, %4};"
                 :: "l"(__cvta_generic_to_global(ptr)), "f"(a), "f"(b), "f"(c), "f"(d)
                 : "memory");
}
__device__ __forceinline__ void mma_tf32(float* d, const uint32_t* a, const uint32_t* b) {
    asm volatile(
        "mma.sync.aligned.m16n8k8.row.col.f32.tf32.tf32.f32 "
        "{%0,%1,%2,%3}, {%4,%5,%6,%7}, {%8,%9}, {%0,%1,%2,%3};"
        : "+f"(d[0]), "+f"(d[1]), "+f"(d[2]), "+f"(d[3])
        : "r"(a[0]), "r"(a[1]), "r"(a[2]), "r"(a[3]), "r"(b[0]), "r"(b[1]));
}

// ---------------------------------------------------------------------------
// prep: transpose W[k][in][out] -> g_wt[k][out][in], tf32-rounded; zero stats.
// ---------------------------------------------------------------------------
__global__ __launch_bounds__(256) void prep_kernel(const float* __restrict__ w) {
    const int k = blockIdx.x;
    const int tid = threadIdx.x;
    if (k == 0 && tid < 2 * CCH) g_stats[tid] = 0.0f;
    const float* wk = w + (size_t)k * CCH * CCH;
    uint32_t* dst = (uint32_t*)(g_wt + (size_t)k * CCH * CCH);
    #pragma unroll
    for (int it = 0; it < 16; ++it) {
        int j = tid + it * 256;          // j = n*64 + i
        int n = j >> 6, i = j & 63;
        dst[j] = f2tf32(wk[i * CCH + n]);
    }
}

// ---------------------------------------------------------------------------
// conv: block = (128-pair tile, k). Gather X (tf32) + W tile into smem,
// warp-level tf32 mma.sync GEMM (regs accumulate), shuffle-pack, red.v4 scatter.
// Warp w: rows (w&3)*32 .. +32, cols (w>>2)*32 .. +32 of the 128x64 tile.
// ---------------------------------------------------------------------------
__global__ __launch_bounds__(256) void conv_kernel(
    const float* __restrict__ x,
    const int*   __restrict__ kin,
    const int*   __restrict__ kout,
    float*       __restrict__ out)
{
    extern __shared__ char smem[];
    int*      sIn  = (int*)(smem + SM_SIN);
    int*      sOut = (int*)(smem + SM_SOUT);
    uint32_t* Xsh  = (uint32_t*)(smem + SM_X);   // [128][XPAD]
    uint32_t* Wsh  = (uint32_t*)(smem + SM_W);   // [64][XPAD], row = n, col = kk

    const int tid  = threadIdx.x;
    const int warp = tid >> 5;
    const int lane = tid & 31;
    const int k     = blockIdx.y;
    const int pbase = blockIdx.x * TP;

    if (tid < TP) {
        int p = pbase + tid;
        bool v = (p < NP);
        sIn[tid]  = v ? kin[(size_t)k * NP + p]  : -1;
        sOut[tid] = v ? kout[(size_t)k * NP + p] : 0;
    }
    __syncthreads();

    // ---- gather A rows (tf32-round): thread -> (row = tid>>1, half = tid&1) ----
    {
        int row = tid >> 1;
        int q   = tid & 1;
        int in  = sIn[row];
        uint32_t* dst = Xsh + row * XPAD + q * 32;
        if (in >= 0) {
            const float4* src = (const float4*)(x + (size_t)in * CCH + q * 32);
            #pragma unroll
            for (int jj = 0; jj < 8; ++jj) {
                float4 v = src[jj];
                uint4 t;
                t.x = f2tf32(v.x); t.y = f2tf32(v.y); t.z = f2tf32(v.z); t.w = f2tf32(v.w);
                *(uint4*)(dst + jj * 4) = t;
            }
        } else {
            uint4 z = make_uint4(0, 0, 0, 0);
            #pragma unroll
            for (int jj = 0; jj < 8; ++jj) *(uint4*)(dst + jj * 4) = z;
        }
    }
    // ---- load Wt[k] tile (pre-rounded): 64 rows x 16 float4 ----
    {
        const uint4* src = (const uint4*)(g_wt + (size_t)k * CCH * CCH);
        #pragma unroll
        for (int r = 0; r < 4; ++r) {
            int idx = tid + r * 256;      // 0..1023
            int row = idx >> 4;
            int jj  = idx & 15;
            *(uint4*)(Wsh + row * XPAD + jj * 4) = src[row * 16 + jj];
        }
    }
    __syncthreads();

    // ---- warp GEMM: 2 mtiles x 4 ntiles x 8 ktiles of m16n8k8 ----
    const int m0 = (warp & 3) * 32;
    const int n0 = (warp >> 2) * 32;
    const int g  = lane >> 2;            // 0..7
    const int t4 = lane & 3;             // 0..3

    float acc[2][4][4];
    #pragma unroll
    for (int mt = 0; mt < 2; ++mt)
        #pragma unroll
        for (int nt = 0; nt < 4; ++nt)
            #pragma unroll
            for (int e = 0; e < 4; ++e) acc[mt][nt][e] = 0.0f;

    #pragma unroll
    for (int kt = 0; kt < 8; ++kt) {
        const int kc = kt * 8 + t4;
        uint32_t a[2][4];
        #pragma unroll
        for (int mt = 0; mt < 2; ++mt) {
            const uint32_t* base = Xsh + (m0 + mt * 16 + g) * XPAD + kc;
            a[mt][0] = base[0];
            a[mt][1] = base[8 * XPAD];
            a[mt][2] = base[4];
            a[mt][3] = base[8 * XPAD + 4];
        }
        uint32_t b[4][2];
        #pragma unroll
        for (int nt = 0; nt < 4; ++nt) {
            const uint32_t* base = Wsh + (n0 + nt * 8 + g) * XPAD + kc;
            b[nt][0] = base[0];
            b[nt][1] = base[4];
        }
        #pragma unroll
        for (int mt = 0; mt < 2; ++mt)
            #pragma unroll
            for (int nt = 0; nt < 4; ++nt)
                mma_tf32(acc[mt][nt], a[mt], b[nt]);
    }

    // ---- epilogue: shuffle-pack into 4 contiguous cols, red.v4 scatter ----
    // D frag: c0=(g, 2t), c1=(g, 2t+1), c2=(g+8, 2t), c3=(g+8, 2t+1).
    // After xor-1 exchange: even lane owns row g cols [cb, cb+4), odd lane owns
    // row g+8 cols [cb, cb+4), where cb = nt*8 + (t4>>1)*4.
    const bool evenl = (lane & 1) == 0;
    const int  cb0   = n0 + (t4 >> 1) * 4;
    #pragma unroll
    for (int mt = 0; mt < 2; ++mt) {
        #pragma unroll
        for (int nt = 0; nt < 4; ++nt) {
            float c0 = acc[mt][nt][0], c1 = acc[mt][nt][1];
            float c2 = acc[mt][nt][2], c3 = acc[mt][nt][3];
            float s0 = __shfl_xor_sync(0xffffffffu, c0, 1);
            float s1 = __shfl_xor_sync(0xffffffffu, c1, 1);
            float s2 = __shfl_xor_sync(0xffffffffu, c2, 1);
            float s3 = __shfl_xor_sync(0xffffffffu, c3, 1);
            float v0, v1, v2, v3;
            int   mrow;
            if (evenl) {                 // row g: my c0,c1 are cols cb,cb+1; partner's c0,c1 are cb+2,cb+3
                v0 = c0; v1 = c1; v2 = s0; v3 = s1;
                mrow = m0 + mt * 16 + g;
            } else {                     // row g+8: partner's c2,c3 are cols cb,cb+1; mine are cb+2,cb+3
                v0 = s2; v1 = s3; v2 = c2; v3 = c3;
                mrow = m0 + mt * 16 + g + 8;
            }
            int o = sOut[mrow];
            red_add_v4(out + (size_t)o * CCH + cb0 + nt * 8, v0, v1, v2, v3);
        }
    }
}

// ---------------------------------------------------------------------------
// BN stats + fused normalize (unchanged)
// ---------------------------------------------------------------------------
__global__ __launch_bounds__(256) void stats_kernel(const float* __restrict__ y) {
    __shared__ float4 shs[256];
    __shared__ float4 shq[256];
    const int tid = threadIdx.x;
    const int cg  = tid & 15;
    const int r0  = tid >> 4;
    float4 s = make_float4(0.f, 0.f, 0.f, 0.f);
    float4 q = make_float4(0.f, 0.f, 0.f, 0.f);
    const float4* y4 = (const float4*)y;
    for (int row = blockIdx.x * 16 + r0; row < NVOX; row += gridDim.x * 16) {
        float4 v = y4[row * 16 + cg];
        s.x += v.x; s.y += v.y; s.z += v.z; s.w += v.w;
        q.x += v.x * v.x; q.y += v.y * v.y; q.z += v.z * v.z; q.w += v.w * v.w;
    }
    shs[tid] = s; shq[tid] = q;
    __syncthreads();
    #pragma unroll
    for (int off = 128; off >= 16; off >>= 1) {
        if (tid < off) {
            float4 a = shs[tid], b = shs[tid + off];
            a.x += b.x; a.y += b.y; a.z += b.z; a.w += b.w; shs[tid] = a;
            float4 c = shq[tid], d = shq[tid + off];
            c.x += d.x; c.y += d.y; c.z += d.z; c.w += d.w; shq[tid] = c;
        }
        __syncthreads();
    }
    if (tid < 16) {
        float4 a = shs[tid], c = shq[tid];
        int col = tid * 4;
        atomicAdd(&g_stats[col + 0], a.x);
        atomicAdd(&g_stats[col + 1], a.y);
        atomicAdd(&g_stats[col + 2], a.z);
        atomicAdd(&g_stats[col + 3], a.w);
        atomicAdd(&g_stats[CCH + col + 0], c.x);
        atomicAdd(&g_stats[CCH + col + 1], c.y);
        atomicAdd(&g_stats[CCH + col + 2], c.z);
        atomicAdd(&g_stats[CCH + col + 3], c.w);
    }
}

__global__ __launch_bounds__(256) void norm_kernel(
    float* __restrict__ y, const float* __restrict__ gamma, const float* __restrict__ beta)
{
    __shared__ float sc[CCH];
    __shared__ float bi[CCH];
    const int tid = threadIdx.x;
    if (tid < CCH) {
        const float invN = 1.0f / (float)NVOX;
        float mean = g_stats[tid] * invN;
        float var  = g_stats[CCH + tid] * invN - mean * mean;
        float s = rsqrtf(var + 1e-5f) * gamma[tid];
        sc[tid] = s;
        bi[tid] = beta[tid] - mean * s;
    }
    __syncthreads();
    const int total4 = NVOX * 16;
    float4* y4 = (float4*)y;
    for (int idx = blockIdx.x * 256 + tid; idx < total4; idx += gridDim.x * 256) {
        int c = (idx & 15) * 4;
        float4 v = y4[idx];
        v.x = fmaxf(fmaf(v.x, sc[c + 0], bi[c + 0]), 0.f);
        v.y = fmaxf(fmaf(v.y, sc[c + 1], bi[c + 1]), 0.f);
        v.z = fmaxf(fmaf(v.z, sc[c + 2], bi[c + 2]), 0.f);
        v.w = fmaxf(fmaf(v.w, sc[c + 3], bi[c + 3]), 0.f);
        y4[idx] = v;
    }
}

// ---------------------------------------------------------------------------
extern "C" void kernel_launch(void* const* d_in, const int* in_sizes, int n_in,
                              void* d_out, int out_size) {
    const float* x     = (const float*)d_in[0];
    const float* w     = (const float*)d_in[1];
    const float* gamma = (const float*)d_in[2];
    const float* beta  = (const float*)d_in[3];
    const int*   kin   = (const int*)d_in[4];
    const int*   kout  = (const int*)d_in[5];
    float*       out   = (float*)d_out;

    cudaFuncSetAttribute(conv_kernel, cudaFuncAttributeMaxDynamicSharedMemorySize, SMEM_TOTAL);

    cudaMemsetAsync(out, 0, (size_t)NVOX * CCH * sizeof(float), 0);
    prep_kernel<<<KK, 256>>>(w);
    conv_kernel<<<dim3(NBLK, KK), 256, SMEM_TOTAL>>>(x, kin, kout, out);
    stats_kernel<<<512, 256>>>(out);
    norm_kernel<<<2048, 256>>>(out, gamma, beta);
}